// round 9
// baseline (speedup 1.0000x reference)
#include <cuda_runtime.h>
#include <cuda_fp16.h>
#include <cstdint>

// ---------------------------------------------------------------------------
// GCN: fp16 feature gather with 4-wide HADD2 tree (conversion-amortized),
// fp32 accumulation, tf32 tensor-core GEMMs.
//   xh   = fp16(x * out_norm)
//   agg1 = fp32(tree4sum_h(xh)) * in_norm
//   h1h  = fp16(relu(agg1 @ w1 + b1) * out_norm)
//   agg2 = fp32(tree4sum_h(h1h)) * in_norm
//   h2   = relu(agg2 @ w2 + b2)
//   h3   = relu(h2 @ wm1 + bm1)
//   out  = h3 @ wm2 + bm2
// CSR built per-launch: histogram -> single-block scan -> bucket scatter.
// ---------------------------------------------------------------------------

#define N_MAX 100000
#define E_MAX 3200000

__device__ int    g_deg_in[N_MAX];
__device__ int    g_deg_out[N_MAX];
__device__ int    g_row_ptr[N_MAX + 1];
__device__ int    g_cursor[N_MAX];
__device__ int    g_sorted_src[E_MAX];
__device__ float  g_out_norm[N_MAX];
__device__ float  g_in_norm[N_MAX];
__device__ __half g_xh[(size_t)N_MAX * 128];
__device__ __half g_h1h[(size_t)N_MAX * 128];
__device__ float  g_agg[(size_t)N_MAX * 128];
__device__ float  g_h[(size_t)N_MAX * 128];
__device__ float  g_h3[(size_t)N_MAX * 256];

// ---------------------------------------------------------------------------
__global__ void zero_deg_kernel(int n, int* deg_in, int* deg_out) {
    int i = blockIdx.x * blockDim.x + threadIdx.x;
    if (i < n) { deg_in[i] = 0; deg_out[i] = 0; }
}

// 4 edges per thread via int4 loads.
__global__ void hist_kernel(int e4, int e, const int* __restrict__ src,
                            const int* __restrict__ dst,
                            int* deg_in, int* deg_out) {
    int i = blockIdx.x * blockDim.x + threadIdx.x;
    if (i < e4) {
        int4 s = *reinterpret_cast<const int4*>(src + i * 4);
        int4 d = *reinterpret_cast<const int4*>(dst + i * 4);
        atomicAdd(&deg_out[s.x], 1); atomicAdd(&deg_in[d.x], 1);
        atomicAdd(&deg_out[s.y], 1); atomicAdd(&deg_in[d.y], 1);
        atomicAdd(&deg_out[s.z], 1); atomicAdd(&deg_in[d.z], 1);
        atomicAdd(&deg_out[s.w], 1); atomicAdd(&deg_in[d.w], 1);
    } else {
        // tail (e not multiple of 4)
        for (int j = e4 * 4 + (i - e4); j < e; j += 1 << 30) {
            atomicAdd(&deg_out[src[j]], 1);
            atomicAdd(&deg_in[dst[j]], 1);
            break;
        }
    }
}

// Single-block exclusive scan, 4 elements per thread per chunk (4096/chunk).
__global__ void scan_kernel(int n, const int* __restrict__ deg, int* __restrict__ row_ptr) {
    __shared__ int wsum[32];
    __shared__ int s_carry;
    const int tid = threadIdx.x;
    const int lane = tid & 31;
    const int wid = tid >> 5;
    if (tid == 0) s_carry = 0;
    __syncthreads();
    for (int base = 0; base < n; base += 4096) {
        int i0 = base + tid * 4;
        int v0 = (i0 + 0 < n) ? deg[i0 + 0] : 0;
        int v1 = (i0 + 1 < n) ? deg[i0 + 1] : 0;
        int v2 = (i0 + 2 < n) ? deg[i0 + 2] : 0;
        int v3 = (i0 + 3 < n) ? deg[i0 + 3] : 0;
        int t = v0 + v1 + v2 + v3;
        int x = t;
        #pragma unroll
        for (int o = 1; o < 32; o <<= 1) {
            int u = __shfl_up_sync(0xffffffffu, x, o);
            if (lane >= o) x += u;
        }
        if (lane == 31) wsum[wid] = x;
        __syncthreads();
        if (wid == 0) {
            int y = wsum[lane];
            #pragma unroll
            for (int o = 1; o < 32; o <<= 1) {
                int u = __shfl_up_sync(0xffffffffu, y, o);
                if (lane >= o) y += u;
            }
            wsum[lane] = y;
        }
        __syncthreads();
        int wofs = (wid > 0) ? wsum[wid - 1] : 0;
        int carry = s_carry;
        int excl = carry + wofs + (x - t);
        if (i0 + 0 < n) row_ptr[i0 + 0] = excl;
        if (i0 + 1 < n) row_ptr[i0 + 1] = excl + v0;
        if (i0 + 2 < n) row_ptr[i0 + 2] = excl + v0 + v1;
        if (i0 + 3 < n) row_ptr[i0 + 3] = excl + v0 + v1 + v2;
        __syncthreads();
        if (tid == 1023) s_carry = carry + wsum[31];
        __syncthreads();
    }
    if (threadIdx.x == 0) row_ptr[n] = s_carry;
}

__global__ void finalize_kernel(int n, const int* __restrict__ deg_out,
                                const int* __restrict__ deg_in,
                                const int* __restrict__ row_ptr,
                                float* out_norm, float* in_norm, int* cursor) {
    int i = blockIdx.x * blockDim.x + threadIdx.x;
    if (i < n) {
        out_norm[i] = rsqrtf((float)max(deg_out[i], 1));
        in_norm[i]  = rsqrtf((float)max(deg_in[i], 1));
        cursor[i]   = row_ptr[i];
    }
}

// 4 edges per thread via int4 loads.
__global__ void scatter_kernel(int e4, int e, const int* __restrict__ src,
                               const int* __restrict__ dst,
                               int* cursor, int* __restrict__ sorted_src) {
    int i = blockIdx.x * blockDim.x + threadIdx.x;
    if (i < e4) {
        int4 s = *reinterpret_cast<const int4*>(src + i * 4);
        int4 d = *reinterpret_cast<const int4*>(dst + i * 4);
        sorted_src[atomicAdd(&cursor[d.x], 1)] = s.x;
        sorted_src[atomicAdd(&cursor[d.y], 1)] = s.y;
        sorted_src[atomicAdd(&cursor[d.z], 1)] = s.z;
        sorted_src[atomicAdd(&cursor[d.w], 1)] = s.w;
    } else {
        int j = e4 * 4 + (i - e4);
        if (j < e) {
            int d = dst[j];
            sorted_src[atomicAdd(&cursor[d], 1)] = src[j];
        }
    }
}

// xh[i, :] = fp16(x[i, :] * out_norm[i]); one thread per 4 features.
__global__ void convert_x_kernel(int n, const float* __restrict__ x,
                                 const float* __restrict__ onorm,
                                 __half* __restrict__ xh) {
    int idx = blockIdx.x * blockDim.x + threadIdx.x;
    if (idx >= n * 32) return;
    int row = idx >> 5;
    float s = onorm[row];
    float4 v = *reinterpret_cast<const float4*>(x + (size_t)idx * 4);
    __half2 o0 = __floats2half2_rn(v.x * s, v.y * s);
    __half2 o1 = __floats2half2_rn(v.z * s, v.w * s);
    uint2 ov;
    ov.x = *reinterpret_cast<uint32_t*>(&o0);
    ov.y = *reinterpret_cast<uint32_t*>(&o1);
    *reinterpret_cast<uint2*>(xh + (size_t)idx * 4) = ov;
}

// ---------------------------------------------------------------------------
__device__ __forceinline__ __half2 u2h(uint32_t u) {
    __half2 h;
    *reinterpret_cast<uint32_t*>(&h) = u;
    return h;
}

// fp16 gather aggregation, 4-wide HADD2 tree: one warp per node; lane l owns
// features [4l, 4l+4). 4 edges summed in fp16 (2 HADD2 levels), one convert
// per 4 edges, fp32 accumulate. out *= in_norm.
__global__ void agg_htree_kernel(int n, const __half* __restrict__ feat,
                                 const int* __restrict__ row_ptr,
                                 const int* __restrict__ srcs,
                                 const float* __restrict__ inorm,
                                 float* __restrict__ out) {
    int warp = (blockIdx.x * blockDim.x + threadIdx.x) >> 5;
    if (warp >= n) return;
    const int lane = threadIdx.x & 31;
    const int beg = row_ptr[warp];
    const int end = row_ptr[warp + 1];
    const __half* fl = feat + lane * 4;

    float a0 = 0.f, a1 = 0.f, a2 = 0.f, a3 = 0.f;
    float b0 = 0.f, b1 = 0.f, b2 = 0.f, b3 = 0.f;

    int i = beg;
    for (; i + 32 <= end; i += 32) {
        int s = __ldg(srcs + i + lane);
        #pragma unroll
        for (int j = 0; j < 32; j += 8) {
            int s0 = __shfl_sync(0xffffffffu, s, j + 0);
            int s1 = __shfl_sync(0xffffffffu, s, j + 1);
            int s2 = __shfl_sync(0xffffffffu, s, j + 2);
            int s3 = __shfl_sync(0xffffffffu, s, j + 3);
            int s4 = __shfl_sync(0xffffffffu, s, j + 4);
            int s5 = __shfl_sync(0xffffffffu, s, j + 5);
            int s6 = __shfl_sync(0xffffffffu, s, j + 6);
            int s7 = __shfl_sync(0xffffffffu, s, j + 7);
            uint2 w0 = *reinterpret_cast<const uint2*>(fl + (size_t)s0 * 128);
            uint2 w1 = *reinterpret_cast<const uint2*>(fl + (size_t)s1 * 128);
            uint2 w2 = *reinterpret_cast<const uint2*>(fl + (size_t)s2 * 128);
            uint2 w3 = *reinterpret_cast<const uint2*>(fl + (size_t)s3 * 128);
            uint2 w4 = *reinterpret_cast<const uint2*>(fl + (size_t)s4 * 128);
            uint2 w5 = *reinterpret_cast<const uint2*>(fl + (size_t)s5 * 128);
            uint2 w6 = *reinterpret_cast<const uint2*>(fl + (size_t)s6 * 128);
            uint2 w7 = *reinterpret_cast<const uint2*>(fl + (size_t)s7 * 128);
            // group A: edges j..j+3, tree sum in fp16
            __half2 pa0 = __hadd2(u2h(w0.x), u2h(w1.x));
            __half2 pa1 = __hadd2(u2h(w0.y), u2h(w1.y));
            __half2 qa0 = __hadd2(u2h(w2.x), u2h(w3.x));
            __half2 qa1 = __hadd2(u2h(w2.y), u2h(w3.y));
            __half2 ra0 = __hadd2(pa0, qa0);
            __half2 ra1 = __hadd2(pa1, qa1);
            // group B: edges j+4..j+7
            __half2 pb0 = __hadd2(u2h(w4.x), u2h(w5.x));
            __half2 pb1 = __hadd2(u2h(w4.y), u2h(w5.y));
            __half2 qb0 = __hadd2(u2h(w6.x), u2h(w7.x));
            __half2 qb1 = __hadd2(u2h(w6.y), u2h(w7.y));
            __half2 rb0 = __hadd2(pb0, qb0);
            __half2 rb1 = __hadd2(pb1, qb1);
            float2 f;
            f = __half22float2(ra0); a0 += f.x; a1 += f.y;
            f = __half22float2(ra1); a2 += f.x; a3 += f.y;
            f = __half22float2(rb0); b0 += f.x; b1 += f.y;
            f = __half22float2(rb1); b2 += f.x; b3 += f.y;
        }
    }
    if (i < end) {
        int cnt = end - i;
        int s = 0;
        if (lane < cnt) s = __ldg(srcs + i + lane);
        int j = 0;
        for (; j + 2 <= cnt; j += 2) {
            int s0 = __shfl_sync(0xffffffffu, s, j + 0);
            int s1 = __shfl_sync(0xffffffffu, s, j + 1);
            uint2 w0 = *reinterpret_cast<const uint2*>(fl + (size_t)s0 * 128);
            uint2 w1 = *reinterpret_cast<const uint2*>(fl + (size_t)s1 * 128);
            __half2 p0 = __hadd2(u2h(w0.x), u2h(w1.x));
            __half2 p1 = __hadd2(u2h(w0.y), u2h(w1.y));
            float2 f;
            f = __half22float2(p0); a0 += f.x; a1 += f.y;
            f = __half22float2(p1); a2 += f.x; a3 += f.y;
        }
        if (j < cnt) {
            int s0 = __shfl_sync(0xffffffffu, s, j);
            uint2 w0 = *reinterpret_cast<const uint2*>(fl + (size_t)s0 * 128);
            float2 f;
            f = __half22float2(u2h(w0.x)); a0 += f.x; a1 += f.y;
            f = __half22float2(u2h(w0.y)); a2 += f.x; a3 += f.y;
        }
    }
    float iw = inorm[warp];
    float4 o = make_float4((a0 + b0) * iw, (a1 + b1) * iw,
                           (a2 + b2) * iw, (a3 + b3) * iw);
    *reinterpret_cast<float4*>(out + (size_t)warp * 128 + lane * 4) = o;
}

// ---------------------------------------------------------------------------
// tf32 tensor-core GEMM via mma.sync.m16n8k8 (proven kernel).
// ---------------------------------------------------------------------------
__device__ __forceinline__ uint32_t f2tf32(float x) {
    uint32_t r;
    asm("cvt.rna.tf32.f32 %0, %1;" : "=r"(r) : "f"(x));
    return r;
}

__device__ __forceinline__ void mma_tf32(float c[4], uint32_t a0, uint32_t a1,
                                         uint32_t a2, uint32_t a3,
                                         uint32_t b0, uint32_t b1) {
    asm volatile(
        "mma.sync.aligned.m16n8k8.row.col.f32.tf32.tf32.f32 "
        "{%0,%1,%2,%3}, {%4,%5,%6,%7}, {%8,%9}, {%0,%1,%2,%3};\n"
        : "+f"(c[0]), "+f"(c[1]), "+f"(c[2]), "+f"(c[3])
        : "r"(a0), "r"(a1), "r"(a2), "r"(a3), "r"(b0), "r"(b1));
}

template <bool RELU, bool PSCALE, bool OUTH>
__global__ __launch_bounds__(256) void gemm_tf32_kernel(
        int M, int K, int ldn,
        const float* __restrict__ A,
        const float* __restrict__ W,
        const float* __restrict__ bias,
        const float* __restrict__ pscale,
        void* __restrict__ Cout) {
    constexpr int BM = 128, BN = 64, BK = 32;
    constexpr int ASTR = BK + 4;
    constexpr int WSTR = BN + 4;
    __shared__ uint32_t As[BM * ASTR];
    __shared__ uint32_t Ws[BK * WSTR];

    const int tid = threadIdx.x;
    const int lane = tid & 31;
    const int wid = tid >> 5;
    const int g = lane >> 2;
    const int tig = lane & 3;
    const int warpM = (wid & 3) * 32;
    const int warpN = (wid >> 2) * 32;
    const int rowBase = blockIdx.x * BM;
    const int nBase = blockIdx.y * BN;

    float4 ra[4];
    float4 rw[2];

    auto loadA = [&](int kb) {
        #pragma unroll
        for (int i = 0; i < 4; i++) {
            int id = tid + i * 256;
            int row = id >> 3;
            int c4 = (id & 7) * 4;
            int grow = rowBase + row;
            if (grow < M)
                ra[i] = *reinterpret_cast<const float4*>(A + (size_t)grow * K + kb + c4);
            else
                ra[i] = make_float4(0.f, 0.f, 0.f, 0.f);
        }
    };
    auto loadW = [&](int kb) {
        #pragma unroll
        for (int i = 0; i < 2; i++) {
            int id = tid + i * 256;
            int row = id >> 4;
            int c4 = (id & 15) * 4;
            rw[i] = *reinterpret_cast<const float4*>(W + (size_t)(kb + row) * ldn + nBase + c4);
        }
    };
    auto storeA = [&]() {
        #pragma unroll
        for (int i = 0; i < 4; i++) {
            int id = tid + i * 256;
            int row = id >> 3;
            int c4 = (id & 7) * 4;
            uint32_t* p = &As[row * ASTR + c4];
            p[0] = f2tf32(ra[i].x);
            p[1] = f2tf32(ra[i].y);
            p[2] = f2tf32(ra[i].z);
            p[3] = f2tf32(ra[i].w);
        }
    };
    auto storeW = [&]() {
        #pragma unroll
        for (int i = 0; i < 2; i++) {
            int id = tid + i * 256;
            int row = id >> 4;
            int c4 = (id & 15) * 4;
            uint32_t* p = &Ws[row * WSTR + c4];
            p[0] = f2tf32(rw[i].x);
            p[1] = f2tf32(rw[i].y);
            p[2] = f2tf32(rw[i].z);
            p[3] = f2tf32(rw[i].w);
        }
    };

    float acc[2][4][4];
    #pragma unroll
    for (int m = 0; m < 2; m++)
        #pragma unroll
        for (int n = 0; n < 4; n++)
            #pragma unroll
            for (int q = 0; q < 4; q++) acc[m][n][q] = 0.f;

    loadA(0);
    loadW(0);

    for (int kb = 0; kb < K; kb += BK) {
        storeA();
        storeW();
        __syncthreads();
        if (kb + BK < K) { loadA(kb + BK); loadW(kb + BK); }

        #pragma unroll
        for (int ks = 0; ks < BK; ks += 8) {
            uint32_t af[2][4];
            #pragma unroll
            for (int m = 0; m < 2; m++) {
                int r0 = warpM + m * 16 + g;
                int r1 = r0 + 8;
                af[m][0] = As[r0 * ASTR + ks + tig];
                af[m][1] = As[r1 * ASTR + ks + tig];
                af[m][2] = As[r0 * ASTR + ks + tig + 4];
                af[m][3] = As[r1 * ASTR + ks + tig + 4];
            }
            uint32_t bf[4][2];
            #pragma unroll
            for (int n = 0; n < 4; n++) {
                int cn = warpN + n * 8 + g;
                bf[n][0] = Ws[(ks + tig) * WSTR + cn];
                bf[n][1] = Ws[(ks + tig + 4) * WSTR + cn];
            }
            #pragma unroll
            for (int m = 0; m < 2; m++)
                #pragma unroll
                for (int n = 0; n < 4; n++)
                    mma_tf32(acc[m][n], af[m][0], af[m][1], af[m][2], af[m][3],
                             bf[n][0], bf[n][1]);
        }
        __syncthreads();
    }

    #pragma unroll
    for (int n = 0; n < 4; n++) {
        int col = nBase + warpN + n * 8 + tig * 2;
        float bv0 = bias[col];
        float bv1 = bias[col + 1];
        #pragma unroll
        for (int m = 0; m < 2; m++) {
            #pragma unroll
            for (int hf = 0; hf < 2; hf++) {
                int row = rowBase + warpM + m * 16 + g + hf * 8;
                if (row >= M) continue;
                float sc = PSCALE ? pscale[row] : 1.f;
                float o0 = acc[m][n][hf * 2 + 0] + bv0;
                float o1 = acc[m][n][hf * 2 + 1] + bv1;
                if (RELU) { o0 = fmaxf(o0, 0.f); o1 = fmaxf(o1, 0.f); }
                o0 *= sc; o1 *= sc;
                if (OUTH) {
                    __half2 o = __floats2half2_rn(o0, o1);
                    *reinterpret_cast<__half2*>((__half*)Cout + (size_t)row * ldn + col) = o;
                } else {
                    *reinterpret_cast<float2*>((float*)Cout + (size_t)row * ldn + col) =
                        make_float2(o0, o1);
                }
            }
        }
    }
}

// ---------------------------------------------------------------------------
extern "C" void kernel_launch(void* const* d_in, const int* in_sizes, int n_in,
                              void* d_out, int out_size) {
    const float* x   = (const float*)d_in[0];
    const int*   src = (const int*)d_in[1];
    const int*   dst = (const int*)d_in[2];
    const float* w1  = (const float*)d_in[3];
    const float* b1  = (const float*)d_in[4];
    const float* w2  = (const float*)d_in[5];
    const float* b2  = (const float*)d_in[6];
    const float* wm1 = (const float*)d_in[7];
    const float* bm1 = (const float*)d_in[8];
    const float* wm2 = (const float*)d_in[9];
    const float* bm2 = (const float*)d_in[10];

    const int n = in_sizes[0] / 128;
    const int e = in_sizes[1];
    const int e4 = e / 4;
    const int tail = e - e4 * 4;

    int *deg_in, *deg_out, *row_ptr, *cursor, *sorted_src;
    float *onorm, *inorm, *agg, *h, *h3;
    __half *xh, *h1h;
    cudaGetSymbolAddress((void**)&deg_in, g_deg_in);
    cudaGetSymbolAddress((void**)&deg_out, g_deg_out);
    cudaGetSymbolAddress((void**)&row_ptr, g_row_ptr);
    cudaGetSymbolAddress((void**)&cursor, g_cursor);
    cudaGetSymbolAddress((void**)&sorted_src, g_sorted_src);
    cudaGetSymbolAddress((void**)&onorm, g_out_norm);
    cudaGetSymbolAddress((void**)&inorm, g_in_norm);
    cudaGetSymbolAddress((void**)&xh, g_xh);
    cudaGetSymbolAddress((void**)&h1h, g_h1h);
    cudaGetSymbolAddress((void**)&agg, g_agg);
    cudaGetSymbolAddress((void**)&h, g_h);
    cudaGetSymbolAddress((void**)&h3, g_h3);

    const int nb = (n + 255) / 256;
    const int eb4 = (e4 + tail + 511) / 512;

    // --- CSR build ---
    zero_deg_kernel<<<nb, 256>>>(n, deg_in, deg_out);
    hist_kernel<<<eb4, 512>>>(e4, e, src, dst, deg_in, deg_out);
    scan_kernel<<<1, 1024>>>(n, deg_in, row_ptr);
    finalize_kernel<<<nb, 256>>>(n, deg_out, deg_in, row_ptr, onorm, inorm, cursor);
    scatter_kernel<<<eb4, 512>>>(e4, e, src, dst, cursor, sorted_src);

    // --- x -> fp16 prescaled by out_norm ---
    convert_x_kernel<<<(n * 32 + 255) / 256, 256>>>(n, x, onorm, xh);

    const int aggBlocks = (n + 7) / 8;
    const dim3 g2((n + 127) / 128, 2);
    const dim3 g4((n + 127) / 128, 4);
    const dim3 g1((n + 127) / 128, 1);

    // --- conv1 ---
    agg_htree_kernel<<<aggBlocks, 256>>>(n, xh, row_ptr, sorted_src, inorm, agg);
    gemm_tf32_kernel<true, true, true><<<g2, 256>>>(n, 128, 128, agg, w1, b1, onorm, h1h);

    // --- conv2 ---
    agg_htree_kernel<<<aggBlocks, 256>>>(n, h1h, row_ptr, sorted_src, inorm, agg);
    gemm_tf32_kernel<true, false, false><<<g2, 256>>>(n, 128, 128, agg, w2, b2, nullptr, h);

    // --- MLP ---
    gemm_tf32_kernel<true, false, false><<<g4, 256>>>(n, 128, 256, h, wm1, bm1, nullptr, h3);
    gemm_tf32_kernel<false, false, false><<<g1, 256>>>(n, 256, 64, h3, wm2, bm2, nullptr, d_out);
}